// round 6
// baseline (speedup 1.0000x reference)
#include <cuda_runtime.h>
#include <cstdint>

// CenterLoss: loss = (sum_i ||x_i - c_{labels_i}||^2) / B + (C-1)*1e-12
// Only the true-label column of the reference's BxC distmat survives the mask;
// masked entries clamp to 1e-12 -> closed-form (C-1)*1e-12 constant.
//
// R6: 1 row per warp, 1024 blocks x 128 threads -> near-perfect wave balance
// (6.92 blocks/SM on 148 SMs) and high occupancy; 8 independent float4 loads
// per lane; label load overlapped with x loads.

#define CLAMP_MIN 1e-12f
#define CLAMP_MAX 1e12f

#define WARPS_PER_BLOCK 4
#define THREADS (WARPS_PER_BLOCK * 32)

__global__ void cl_init_out(float* out, float const_term) {
    *out = const_term;
}

// D = 512 floats = 128 float4 per row; 32 lanes * 4 iters covers a row.
__global__ void __launch_bounds__(THREADS, 12)
cl_row_kernel(const float4* __restrict__ x,
              const int* __restrict__ labels,
              const float4* __restrict__ centers,
              float* __restrict__ out,
              float inv_b, int B, int C)
{
    const int lane = threadIdx.x & 31;
    const int warp = threadIdx.x >> 5;
    const int row  = blockIdx.x * WARPS_PER_BLOCK + warp;

    __shared__ float block_sum;
    if (threadIdx.x == 0) block_sum = 0.0f;
    __syncthreads();

    if (row < B) {
        // Label first (one load per warp, broadcast); x loads are independent
        // of it and issue right behind, hiding the label latency.
        int lab = __shfl_sync(0xFFFFFFFFu, (lane == 0) ? labels[row] : 0, 0);
        lab = min(max(lab, 0), C - 1);

        const float4* xr = x + (size_t)row * 128;
        const float4* cr = centers + (size_t)lab * 128;

        // Issue all 8 loads up front, then compute.
        float4 xa0 = xr[lane];
        float4 xa1 = xr[32 + lane];
        float4 xa2 = xr[64 + lane];
        float4 xa3 = xr[96 + lane];
        float4 ca0 = cr[lane];
        float4 ca1 = cr[32 + lane];
        float4 ca2 = cr[64 + lane];
        float4 ca3 = cr[96 + lane];

        float s = 0.0f, d;
        d = xa0.x - ca0.x; s += d * d;
        d = xa0.y - ca0.y; s += d * d;
        d = xa0.z - ca0.z; s += d * d;
        d = xa0.w - ca0.w; s += d * d;
        d = xa1.x - ca1.x; s += d * d;
        d = xa1.y - ca1.y; s += d * d;
        d = xa1.z - ca1.z; s += d * d;
        d = xa1.w - ca1.w; s += d * d;
        d = xa2.x - ca2.x; s += d * d;
        d = xa2.y - ca2.y; s += d * d;
        d = xa2.z - ca2.z; s += d * d;
        d = xa2.w - ca2.w; s += d * d;
        d = xa3.x - ca3.x; s += d * d;
        d = xa3.y - ca3.y; s += d * d;
        d = xa3.z - ca3.z; s += d * d;
        d = xa3.w - ca3.w; s += d * d;

        #pragma unroll
        for (int o = 16; o > 0; o >>= 1)
            s += __shfl_xor_sync(0xFFFFFFFFu, s, o);

        if (lane == 0) {
            // Per-row clamp (no-op at typical magnitudes ~1024, kept exact).
            s = fminf(fmaxf(s, CLAMP_MIN), CLAMP_MAX);
            atomicAdd(&block_sum, s);
        }
    }

    __syncthreads();
    if (threadIdx.x == 0)
        atomicAdd(out, block_sum * inv_b);   // no return -> RED
}

extern "C" void kernel_launch(void* const* d_in, const int* in_sizes, int n_in,
                              void* d_out, int out_size)
{
    // Inputs (metadata order): x (B*D f32), labels (B int32), centers (C*D f32)
    const float4* x       = (const float4*)d_in[0];
    const int*    labels  = (const int*)d_in[1];
    const float4* centers = (const float4*)d_in[2];
    float*        out     = (float*)d_out;

    const int B = in_sizes[1];           // 4096
    const int D = in_sizes[0] / B;       // 512
    const int C = in_sizes[2] / D;       // 10000

    const float const_term = (float)((double)(C - 1) * 1e-12);
    const float inv_b = 1.0f / (float)B;

    const int grid = (B + WARPS_PER_BLOCK - 1) / WARPS_PER_BLOCK;  // 1024

    cl_init_out<<<1, 1>>>(out, const_term);
    cl_row_kernel<<<grid, THREADS>>>(x, labels, centers, out, inv_b, B, C);
}